// round 11
// baseline (speedup 1.0000x reference)
#include <cuda_runtime.h>
#include <cuda_fp16.h>
#include <mma.h>
#include <cstdint>
using namespace nvcuda;

// Problem dims (fixed)
#define BB   1024
#define TT   128
#define DD   128
#define HH   8
#define HDIM 16
#define FFD  512
#define NL   2
#define MM   (BB*TT)          // 131072 tokens

// fp16 scratch
__device__ __half g_wqkv[(size_t)NL * 3 * DD * DD];
__device__ __half g_wout[(size_t)NL * DD * DD];
__device__ __half g_wff1[(size_t)NL * FFD * DD];
__device__ __half g_wff2[(size_t)NL * DD * FFD];
__device__ __half g_xh  [(size_t)MM * DD];
__device__ __half g_attnh[(size_t)MM * DD];

// ---------------------------------------------------------------------------
#define N_XH4 (MM * DD / 4)
#define N_WQ4 (NL * 3 * DD * DD / 4)
#define N_WO4 (NL * DD * DD / 4)
#define N_W14 (NL * FFD * DD / 4)
#define N_W24 (NL * DD * FFD / 4)
#define N_CVT (N_XH4 + N_WQ4 + N_WO4 + N_W14 + N_W24)

__global__ void cvt_all(const float* __restrict__ x,
                        const float* __restrict__ wq,
                        const float* __restrict__ wo,
                        const float* __restrict__ w1,
                        const float* __restrict__ w2)
{
    long i = (long)blockIdx.x * blockDim.x + threadIdx.x;
    if (i >= N_CVT) return;
    const float* src;
    __half* dst;
    long off = i;
    if (off < N_XH4)                      { src = x;  dst = g_xh;   }
    else if ((off -= N_XH4) < N_WQ4)      { src = wq; dst = g_wqkv; }
    else if ((off -= N_WQ4) < N_WO4)      { src = wo; dst = g_wout; }
    else if ((off -= N_WO4) < N_W14)      { src = w1; dst = g_wff1; }
    else  { off -= N_W14;                   src = w2; dst = g_wff2; }
    float4 v = ((const float4*)src)[off];
    __half2 h0 = __floats2half2_rn(v.x, v.y);
    __half2 h1 = __floats2half2_rn(v.z, v.w);
    uint2 u;
    u.x = *reinterpret_cast<uint32_t*>(&h0);
    u.y = *reinterpret_cast<uint32_t*>(&h1);
    ((uint2*)dst)[off] = u;
}

__device__ __forceinline__ uint32_t smem_u32(const void* p) {
    uint32_t a;
    asm("{ .reg .u64 t; cvta.to.shared.u64 t, %1; cvt.u32.u64 %0, t; }"
        : "=r"(a) : "l"(p));
    return a;
}
__device__ __forceinline__ void cp16(uint32_t dst, const void* src) {
    asm volatile("cp.async.ca.shared.global [%0], [%1], 16;" :: "r"(dst), "l"(src));
}
__device__ __forceinline__ float fast_exp_s6(float x) {
    x = fmaxf(x, -80.f);
    float t  = x * 1.4426950408889634f;
    float fn = t + 12582912.f;
    int   ni = __float_as_int(fn) - 0x4B400000;
    float r  = t - (fn - 12582912.f);
    float p  = 0.00133336f;
    p = fmaf(p, r, 0.00961813f);
    p = fmaf(p, r, 0.05550411f);
    p = fmaf(p, r, 0.24022651f);
    p = fmaf(p, r, 0.69314718f);
    p = fmaf(p, r, 1.0f);
    return p * __int_as_float((ni + 121) << 23);   // * 2^(n-6)
}

// ===========================================================================
// attn_fused: one CTA per batch b. qkv GEMM into smem + 8-head attention.
// ===========================================================================
#define A_LD    136
#define A_WLD   40
#define A_QS    69632
#define A_KS    104448
#define A_VS    139264
#define A_WBUF  174080
#define A_RB    194560
#define A_SMEM  229376

__global__ __launch_bounds__(256, 1) void attn_fused(
    const __half* __restrict__ xh, const __half* __restrict__ Wq,
    const float* __restrict__ bq, const float* __restrict__ mask,
    __half* __restrict__ outp)
{
    extern __shared__ __align__(16) char sm[];
    const uint32_t sb = smem_u32(sm);
    const int tid  = threadIdx.x;
    const int wid  = tid >> 5;
    const int wm   = wid & 1;
    const int wn   = wid >> 1;
    const int b    = blockIdx.x;
    const size_t bm = (size_t)b * TT;

    // ---- prologue: load x tile (group 0), W tile 0 (group 1)
    {
#pragma unroll
        for (int p = 0; p < 8; p++) {
            int id = p * 256 + tid;
            int row = id >> 4, c = id & 15;
            cp16(sb + row * (A_LD * 2) + c * 16, xh + (bm + row) * DD + c * 8);
        }
        asm volatile("cp.async.commit_group;");
#pragma unroll
        for (int p = 0; p < 2; p++) {
            int id = p * 256 + tid;
            int row = id >> 2, c4 = id & 3;
            cp16(sb + A_WBUF + row * (A_WLD * 2) + c4 * 16, Wq + (size_t)row * DD + c4 * 8);
        }
        asm volatile("cp.async.commit_group;");
    }

    // ---- P1: qkv = x @ Wq^T + bq  -> Qs/Ks/Vs (12 tiles of W, 2-deep ring)
    wmma::fragment<wmma::accumulator, 16, 16, 16, float> acc[4][2];
    const __half* Xs = (const __half*)sm;
    float* stage64 = (float*)(sm + A_RB);

    for (int j = 0; j < 12; j++) {
        if (j < 11) {
            const int jn = j + 1, ncn = jn >> 2, tn = jn & 3;
            const uint32_t wb = sb + A_WBUF + (jn & 1) * 10240;
#pragma unroll
            for (int p = 0; p < 2; p++) {
                int id = p * 256 + tid;
                int row = id >> 2, c4 = id & 3;
                cp16(wb + row * (A_WLD * 2) + c4 * 16,
                     Wq + (size_t)(ncn * 128 + row) * DD + tn * 32 + c4 * 8);
            }
            asm volatile("cp.async.commit_group;");
            asm volatile("cp.async.wait_group 1;");
        } else {
            asm volatile("cp.async.wait_group 0;");
        }
        __syncthreads();

        const int nc = j >> 2, t = j & 3;
        if (t == 0) {
#pragma unroll
            for (int i = 0; i < 4; i++)
#pragma unroll
                for (int jj = 0; jj < 2; jj++) wmma::fill_fragment(acc[i][jj], 0.f);
        }
        {
            const __half* Wb = (const __half*)(sm + A_WBUF + (j & 1) * 10240);
#pragma unroll
            for (int ks = 0; ks < 2; ks++) {
                wmma::fragment<wmma::matrix_a, 16, 16, 16, __half, wmma::row_major> af[4];
                wmma::fragment<wmma::matrix_b, 16, 16, 16, __half, wmma::col_major> bf[2];
#pragma unroll
                for (int i = 0; i < 4; i++)
                    wmma::load_matrix_sync(af[i], Xs + (wm * 64 + i * 16) * A_LD + t * 32 + ks * 16, A_LD);
#pragma unroll
                for (int jj = 0; jj < 2; jj++)
                    wmma::load_matrix_sync(bf[jj], Wb + (wn * 32 + jj * 16) * A_WLD + ks * 16, A_WLD);
#pragma unroll
                for (int i = 0; i < 4; i++)
#pragma unroll
                    for (int jj = 0; jj < 2; jj++)
                        wmma::mma_sync(acc[i][jj], af[i], bf[jj], acc[i][jj]);
            }
        }
        if (t == 3) {
            __half* dst = (__half*)(sm + (nc == 0 ? A_QS : nc == 1 ? A_KS : A_VS));
            const float* bias = bq + nc * 128;
#pragma unroll
            for (int pass = 0; pass < 2; pass++) {
                if (wm == pass) {
#pragma unroll
                    for (int i = 0; i < 4; i++)
#pragma unroll
                        for (int jj = 0; jj < 2; jj++)
                            wmma::store_matrix_sync(stage64 + (i * 16) * 132 + wn * 32 + jj * 16,
                                                    acc[i][jj], 132, wmma::mem_row_major);
                }
                __syncthreads();
#pragma unroll
                for (int q = 0; q < 16; q++) {
                    int id = q * 256 + tid;
                    int r64 = id >> 6, col = (id & 63) * 2;
                    float v0 = stage64[r64 * 132 + col]     + bias[col];
                    float v1 = stage64[r64 * 132 + col + 1] + bias[col + 1];
                    __half2 hv = __floats2half2_rn(v0, v1);
                    *(__half2*)(dst + (pass * 64 + r64) * A_LD + col) = hv;
                }
                __syncthreads();
            }
        }
        __syncthreads();
    }

    // ---- P2: attention (8 heads)
    float* Ss = (float*)sm;                       // [128][68]
    __half* Ps = (__half*)(sm + 34816);           // [128][136]
    const __half* Qs = (const __half*)(sm + A_QS);
    const __half* Ks = (const __half*)(sm + A_KS);
    const __half* Vs = (const __half*)(sm + A_VS);
    float* Of = (float*)(sm + A_RB);              // [128][20]
    float* ms = (float*)(sm + A_RB + 10240);      // [128]
    float* rs = (float*)(sm + A_RB + 10752);      // [128]

    if (tid < TT) ms[tid] = mask[b * TT + tid];
    __syncthreads();

    const int er = tid >> 1;
    const int eh = tid & 1;

    for (int h = 0; h < HH; h++) {
        wmma::fragment<wmma::matrix_a, 16, 16, 16, __half, wmma::row_major> qf;
        wmma::load_matrix_sync(qf, Qs + (wid * 16) * A_LD + h * 16, A_LD);

        float sum = 0.f;
        for (int chunk = 0; chunk < 2; chunk++) {
#pragma unroll
            for (int jj = 0; jj < 4; jj++) {
                wmma::fragment<wmma::matrix_b, 16, 16, 16, __half, wmma::col_major> kf;
                wmma::fragment<wmma::accumulator, 16, 16, 16, float> sf;
                wmma::load_matrix_sync(kf, Ks + (chunk * 64 + jj * 16) * A_LD + h * 16, A_LD);
                wmma::fill_fragment(sf, 0.f);
                wmma::mma_sync(sf, qf, kf, sf);
                wmma::store_matrix_sync(Ss + (wid * 16) * 68 + jj * 16, sf, 68, wmma::mem_row_major);
            }
            __syncthreads();
            {
                const float* srow = Ss + er * 68 + eh * 32;
                __half* prow = Ps + er * 136 + chunk * 64 + eh * 32;
                const float* mrow = ms + chunk * 64 + eh * 32;
#pragma unroll
                for (int c = 0; c < 32; c++) {
                    float p = fast_exp_s6(fmaf(srow[c], 0.25f, mrow[c]));
                    __half ph = __float2half_rn(p);
                    prow[c] = ph;
                    sum += __half2float(ph);
                }
            }
            __syncthreads();
        }
        sum += __shfl_xor_sync(0xffffffffu, sum, 1);
        if (!eh) rs[er] = sum;

        {
            wmma::fragment<wmma::accumulator, 16, 16, 16, float> of;
            wmma::fill_fragment(of, 0.f);
#pragma unroll
            for (int jj = 0; jj < 8; jj++) {
                wmma::fragment<wmma::matrix_a, 16, 16, 16, __half, wmma::row_major> pf;
                wmma::fragment<wmma::matrix_b, 16, 16, 16, __half, wmma::row_major> vf;
                wmma::load_matrix_sync(pf, Ps + (wid * 16) * 136 + jj * 16, 136);
                wmma::load_matrix_sync(vf, Vs + (jj * 16) * A_LD + h * 16, A_LD);
                wmma::mma_sync(of, pf, vf, of);
            }
            wmma::store_matrix_sync(Of + (wid * 16) * 20, of, 20, wmma::mem_row_major);
        }
        __syncthreads();
        {
            const int r = tid >> 1, c0 = (tid & 1) * 8;
            const float inv = 1.f / rs[r];
            const float* orow = Of + r * 20 + c0;
            uint4 u;
            uint32_t* pu = &u.x;
#pragma unroll
            for (int jj = 0; jj < 4; jj++) {
                __half2 hv = __floats2half2_rn(orow[jj * 2] * inv, orow[jj * 2 + 1] * inv);
                pu[jj] = *reinterpret_cast<uint32_t*>(&hv);
            }
            *(uint4*)(outp + (bm + r) * DD + h * HDIM + c0) = u;
        }
        __syncthreads();
    }
}

// ===========================================================================
// ff_fused: one CTA per 128-token tile. X <- LN(X + relu(x@W1^T+b1)@W2^T + b2)
// ===========================================================================
#define F_XS    0
#define F_STG   34816
#define F_HC    69632
#define F_WBUF  88064
#define F_SMEM  108544
#define F_HLD   72

__device__ __forceinline__ void ff_issue(uint32_t sb, const __half* w1,
                                         const __half* w2, int j, int tid)
{
    const int c = j / 6, ph = j % 6;
    const uint32_t wb = sb + F_WBUF + (j & 1) * 10240;
    if (ph < 4) {        // W1 tile: 64 rows x 32k
        int row = tid >> 2, c4 = tid & 3;
        cp16(wb + row * (A_WLD * 2) + c4 * 16,
             w1 + (size_t)(c * 64 + row) * DD + ph * 32 + c4 * 8);
    } else {             // W2 tile: 128 rows x 32k
#pragma unroll
        for (int p = 0; p < 2; p++) {
            int id = p * 256 + tid;
            int row = id >> 2, c4 = id & 3;
            cp16(wb + row * (A_WLD * 2) + c4 * 16,
                 w2 + (size_t)row * FFD + c * 64 + (ph - 4) * 32 + c4 * 8);
        }
    }
    asm volatile("cp.async.commit_group;");
}

__global__ __launch_bounds__(256, 2) void ff_fused(
    const __half* __restrict__ xh, const __half* __restrict__ w1,
    const float* __restrict__ b1, const __half* __restrict__ w2,
    const float* __restrict__ b2,
    float* __restrict__ X, __half* __restrict__ Xh,
    const float* __restrict__ gamma, const float* __restrict__ beta)
{
    extern __shared__ __align__(16) char sm[];
    const uint32_t sb = smem_u32(sm);
    const int tid  = threadIdx.x;
    const int wid  = tid >> 5;
    const int lane = tid & 31;
    const size_t bm = (size_t)blockIdx.x * 128;

    const int wm1 = wid & 3, wn1 = wid >> 2;   // gemm1: 4x2 warp grid, 32x32 tiles
    const int wm2 = wid & 1, wn2 = wid >> 1;   // gemm2: 2x4 warp grid, 64x32 tiles

    {
#pragma unroll
        for (int p = 0; p < 8; p++) {
            int id = p * 256 + tid;
            int row = id >> 4, c = id & 15;
            cp16(sb + F_XS + row * (A_LD * 2) + c * 16, xh + (bm + row) * DD + c * 8);
        }
        asm volatile("cp.async.commit_group;");
    }
    ff_issue(sb, w1, w2, 0, tid);

    wmma::fragment<wmma::accumulator, 16, 16, 16, float> acc[4][2];   // FF2 out
#pragma unroll
    for (int i = 0; i < 4; i++)
#pragma unroll
        for (int jj = 0; jj < 2; jj++) wmma::fill_fragment(acc[i][jj], 0.f);
    wmma::fragment<wmma::accumulator, 16, 16, 16, float> acc1[2][2];  // FF1 chunk

    const __half* Xs = (const __half*)(sm + F_XS);
    float* stg = (float*)(sm + F_STG);
    __half* hc = (__half*)(sm + F_HC);

    for (int j = 0; j < 48; j++) {
        if (j < 47) {
            ff_issue(sb, w1, w2, j + 1, tid);
            asm volatile("cp.async.wait_group 1;");
        } else {
            asm volatile("cp.async.wait_group 0;");
        }
        __syncthreads();

        const int c = j / 6, ph = j % 6;
        const __half* Wb = (const __half*)(sm + F_WBUF + (j & 1) * 10240);
        if (ph < 4) {
            if (ph == 0) {
#pragma unroll
                for (int i = 0; i < 2; i++)
#pragma unroll
                    for (int jj = 0; jj < 2; jj++) wmma::fill_fragment(acc1[i][jj], 0.f);
            }
#pragma unroll
            for (int ks = 0; ks < 2; ks++) {
                wmma::fragment<wmma::matrix_a, 16, 16, 16, __half, wmma::row_major> af[2];
                wmma::fragment<wmma::matrix_b, 16, 16, 16, __half, wmma::col_major> bf[2];
#pragma unroll
                for (int i = 0; i < 2; i++)
                    wmma::load_matrix_sync(af[i], Xs + (wm1 * 32 + i * 16) * A_LD + ph * 32 + ks * 16, A_LD);
#pragma unroll
                for (int jj = 0; jj < 2; jj++)
                    wmma::load_matrix_sync(bf[jj], Wb + (wn1 * 32 + jj * 16) * A_WLD + ks * 16, A_WLD);
#pragma unroll
                for (int i = 0; i < 2; i++)
#pragma unroll
                    for (int jj = 0; jj < 2; jj++)
                        wmma::mma_sync(acc1[i][jj], af[i], bf[jj], acc1[i][jj]);
            }
            if (ph == 3) {
#pragma unroll
                for (int i = 0; i < 2; i++)
#pragma unroll
                    for (int jj = 0; jj < 2; jj++)
                        wmma::store_matrix_sync(stg + (wm1 * 32 + i * 16) * 68 + wn1 * 32 + jj * 16,
                                                acc1[i][jj], 68, wmma::mem_row_major);
                __syncthreads();
                const float* bc = b1 + c * 64;
#pragma unroll
                for (int q = 0; q < 16; q++) {          // FIX: 16 (was 8) -> all 128 rows
                    int id = q * 256 + tid;
                    int row = id >> 5, col = (id & 31) * 2;
                    float v0 = fmaxf(stg[row * 68 + col]     + bc[col],     0.f);
                    float v1 = fmaxf(stg[row * 68 + col + 1] + bc[col + 1], 0.f);
                    *(__half2*)(hc + row * F_HLD + col) = __floats2half2_rn(v0, v1);
                }
            }
        } else {
            const int t2 = ph - 4;
#pragma unroll
            for (int ks = 0; ks < 2; ks++) {
                wmma::fragment<wmma::matrix_a, 16, 16, 16, __half, wmma::row_major> af[4];
                wmma::fragment<wmma::matrix_b, 16, 16, 16, __half, wmma::col_major> bf[2];
#pragma unroll
                for (int i = 0; i < 4; i++)
                    wmma::load_matrix_sync(af[i], hc + (wm2 * 64 + i * 16) * F_HLD + t2 * 32 + ks * 16, F_HLD);
#pragma unroll
                for (int jj = 0; jj < 2; jj++)
                    wmma::load_matrix_sync(bf[jj], Wb + (wn2 * 32 + jj * 16) * A_WLD + ks * 16, A_WLD);
#pragma unroll
                for (int i = 0; i < 4; i++)
#pragma unroll
                    for (int jj = 0; jj < 2; jj++)
                        wmma::mma_sync(acc[i][jj], af[i], bf[jj], acc[i][jj]);
            }
        }
        __syncthreads();
    }

    // ---- epilogue: residual + LN (2 passes of 64 rows via stage[64][132])
    float* s64 = (float*)(sm + F_STG);
    float4 gv = *(const float4*)(gamma + lane * 4);
    float4 bv = *(const float4*)(beta  + lane * 4);
    float4 bz = *(const float4*)(b2    + lane * 4);
#pragma unroll
    for (int pass = 0; pass < 2; pass++) {
        if (wm2 == pass) {
#pragma unroll
            for (int i = 0; i < 4; i++)
#pragma unroll
                for (int jj = 0; jj < 2; jj++)
                    wmma::store_matrix_sync(s64 + (i * 16) * 132 + wn2 * 32 + jj * 16,
                                            acc[i][jj], 132, wmma::mem_row_major);
        }
        __syncthreads();
#pragma unroll
        for (int rr = 0; rr < 8; rr++) {
            const int r64 = wid * 8 + rr;
            float4 v = *(float4*)(s64 + r64 * 132 + lane * 4);
            const size_t off = (bm + pass * 64 + r64) * DD + lane * 4;
            float4 xv = *(const float4*)(X + off);
            float4 tv;
            tv.x = v.x + bz.x + xv.x; tv.y = v.y + bz.y + xv.y;
            tv.z = v.z + bz.z + xv.z; tv.w = v.w + bz.w + xv.w;
            float s  = tv.x + tv.y + tv.z + tv.w;
            float s2 = tv.x*tv.x + tv.y*tv.y + tv.z*tv.z + tv.w*tv.w;
#pragma unroll
            for (int o = 16; o > 0; o >>= 1) {
                s  += __shfl_xor_sync(0xffffffffu, s,  o);
                s2 += __shfl_xor_sync(0xffffffffu, s2, o);
            }
            float mean = s * (1.f / DD);
            float var  = s2 * (1.f / DD) - mean * mean;
            float rstd = rsqrtf(var + 1e-5f);
            float4 y;
            y.x = (tv.x - mean) * rstd * gv.x + bv.x;
            y.y = (tv.y - mean) * rstd * gv.y + bv.y;
            y.z = (tv.z - mean) * rstd * gv.z + bv.z;
            y.w = (tv.w - mean) * rstd * gv.w + bv.w;
            *(float4*)(X + off) = y;
            __half2 h0 = __floats2half2_rn(y.x, y.y);
            __half2 h1 = __floats2half2_rn(y.z, y.w);
            uint2 u;
            u.x = *reinterpret_cast<uint32_t*>(&h0);
            u.y = *reinterpret_cast<uint32_t*>(&h1);
            *(uint2*)(Xh + off) = u;
        }
        __syncthreads();
    }
}

// ---------------------------------------------------------------------------
// gemm_h (R9 proven): used for out-proj + LN1 (mode 2).
// ---------------------------------------------------------------------------
#define BK   32
#define ALD  40
#define STG_B 20480
#define NS   4
#define CLD  132
#define SMEM_DYN (NS*STG_B)

__global__ __launch_bounds__(256, 2) void gemm_h(
    const __half* __restrict__ A, const __half* __restrict__ W,
    const float* __restrict__ bias,
    __half* __restrict__ Ch,
    float* __restrict__ X, __half* __restrict__ Xh,
    const float* __restrict__ gamma, const float* __restrict__ beta,
    int N, int K, int mode)
{
    extern __shared__ __align__(16) char smem[];
    const uint32_t sbase = smem_u32(smem);
    const int tid  = threadIdx.x;
    const int wid  = tid >> 5;
    const int lane = tid & 31;
    const int wm   = wid & 1;
    const int wn   = wid >> 1;
    const size_t bm = (size_t)blockIdx.y * 128;
    const size_t bn = (size_t)blockIdx.x * 128;
    const int NT = K / BK;

    const int rA0 = tid >> 2, cA0 = tid & 3;
    const int rA1 = (tid + 256) >> 2, cA1 = (tid + 256) & 3;

    wmma::fragment<wmma::accumulator, 16, 16, 16, float> acc[4][2];
#pragma unroll
    for (int i = 0; i < 4; i++)
#pragma unroll
        for (int j = 0; j < 2; j++) wmma::fill_fragment(acc[i][j], 0.f);

#pragma unroll
    for (int t = 0; t < NS - 1; t++) {
        if (t < NT) {
            const int kk = t * BK;
            const uint32_t sb = sbase + (t % NS) * STG_B;
            cp16(sb + (rA0 * ALD + cA0 * 8) * 2, A + (bm + rA0) * K + kk + cA0 * 8);
            cp16(sb + (rA1 * ALD + cA1 * 8) * 2, A + (bm + rA1) * K + kk + cA1 * 8);
            cp16(sb + 10240 + (rA0 * ALD + cA0 * 8) * 2, W + (bn + rA0) * K + kk + cA0 * 8);
            cp16(sb + 10240 + (rA1 * ALD + cA1 * 8) * 2, W + (bn + rA1) * K + kk + cA1 * 8);
        }
        asm volatile("cp.async.commit_group;");
    }

    for (int t = 0; t < NT; t++) {
        asm volatile("cp.async.wait_group %0;" :: "n"(NS - 2));
        __syncthreads();
        {
            const __half* As = (const __half*)(smem + (t % NS) * STG_B);
            const __half* Ws = As + 5120;
#pragma unroll
            for (int ks = 0; ks < 2; ks++) {
                wmma::fragment<wmma::matrix_a, 16, 16, 16, __half, wmma::row_major> af[4];
                wmma::fragment<wmma::matrix_b, 16, 16, 16, __half, wmma::col_major> bf[2];
#pragma unroll
                for (int i = 0; i < 4; i++)
                    wmma::load_matrix_sync(af[i], As + (wm * 64 + i * 16) * ALD + ks * 16, ALD);
#pragma unroll
                for (int j = 0; j < 2; j++)
                    wmma::load_matrix_sync(bf[j], Ws + (wn * 32 + j * 16) * ALD + ks * 16, ALD);
#pragma unroll
                for (int i = 0; i < 4; i++)
#pragma unroll
                    for (int j = 0; j < 2; j++)
                        wmma::mma_sync(acc[i][j], af[i], bf[j], acc[i][j]);
            }
        }
        __syncthreads();
        {
            const int tn = t + NS - 1;
            if (tn < NT) {
                const int kk = tn * BK;
                const uint32_t sb = sbase + (tn % NS) * STG_B;
                cp16(sb + (rA0 * ALD + cA0 * 8) * 2, A + (bm + rA0) * K + kk + cA0 * 8);
                cp16(sb + (rA1 * ALD + cA1 * 8) * 2, A + (bm + rA1) * K + kk + cA1 * 8);
                cp16(sb + 10240 + (rA0 * ALD + cA0 * 8) * 2, W + (bn + rA0) * K + kk + cA0 * 8);
                cp16(sb + 10240 + (rA1 * ALD + cA1 * 8) * 2, W + (bn + rA1) * K + kk + cA1 * 8);
            }
            asm volatile("cp.async.commit_group;");
        }
    }

    float* smf = (float*)smem;
#pragma unroll
    for (int i = 0; i < 4; i++)
#pragma unroll
        for (int j = 0; j < 2; j++)
            wmma::store_matrix_sync(smf + (wm * 64 + i * 16) * CLD + wn * 32 + j * 16,
                                    acc[i][j], CLD, wmma::mem_row_major);
    __syncthreads();

    if (mode == 2) {
        float4 gv = *(const float4*)(gamma + lane * 4);
        float4 bv = *(const float4*)(beta  + lane * 4);
        float4 bz = *(const float4*)(bias  + lane * 4);
#pragma unroll
        for (int i = 0; i < 16; i++) {
            const int row = wid * 16 + i;
            float4 v = *(float4*)(smf + row * CLD + lane * 4);
            const size_t off = (bm + row) * DD + lane * 4;
            float4 xv = *(const float4*)(X + off);
            float4 tv;
            tv.x = v.x + bz.x + xv.x; tv.y = v.y + bz.y + xv.y;
            tv.z = v.z + bz.z + xv.z; tv.w = v.w + bz.w + xv.w;
            float s  = tv.x + tv.y + tv.z + tv.w;
            float s2 = tv.x*tv.x + tv.y*tv.y + tv.z*tv.z + tv.w*tv.w;
#pragma unroll
            for (int o = 16; o > 0; o >>= 1) {
                s  += __shfl_xor_sync(0xffffffffu, s,  o);
                s2 += __shfl_xor_sync(0xffffffffu, s2, o);
            }
            float mean = s * (1.f / DD);
            float var  = s2 * (1.f / DD) - mean * mean;
            float rstd = rsqrtf(var + 1e-5f);
            float4 y;
            y.x = (tv.x - mean) * rstd * gv.x + bv.x;
            y.y = (tv.y - mean) * rstd * gv.y + bv.y;
            y.z = (tv.z - mean) * rstd * gv.z + bv.z;
            y.w = (tv.w - mean) * rstd * gv.w + bv.w;
            *(float4*)(X + off) = y;
            __half2 h0 = __floats2half2_rn(y.x, y.y);
            __half2 h1 = __floats2half2_rn(y.z, y.w);
            uint2 u;
            u.x = *reinterpret_cast<uint32_t*>(&h0);
            u.y = *reinterpret_cast<uint32_t*>(&h1);
            *(uint2*)(Xh + off) = u;
        }
    } else {
#pragma unroll
        for (int i = 0; i < 16; i++) {
            int idx = i * 256 + tid;
            int row = idx >> 5;
            int cc  = (idx & 31) * 4;
            float4 v  = *(float4*)(smf + row * CLD + cc);
            float4 bz = *(const float4*)(bias + bn + cc);
            v.x += bz.x; v.y += bz.y; v.z += bz.z; v.w += bz.w;
            if (mode == 1) {
                v.x = fmaxf(v.x, 0.f); v.y = fmaxf(v.y, 0.f);
                v.z = fmaxf(v.z, 0.f); v.w = fmaxf(v.w, 0.f);
            }
            __half2 h0 = __floats2half2_rn(v.x, v.y);
            __half2 h1 = __floats2half2_rn(v.z, v.w);
            uint2 u;
            u.x = *reinterpret_cast<uint32_t*>(&h0);
            u.y = *reinterpret_cast<uint32_t*>(&h1);
            *(uint2*)(Ch + (bm + row) * N + bn + cc) = u;
        }
    }
}

// ---------------------------------------------------------------------------
extern "C" void kernel_launch(void* const* d_in, const int* in_sizes, int n_in,
                              void* d_out, int out_size)
{
    const float* x_in      = (const float*)d_in[0];
    const float* mask      = (const float*)d_in[1];
    const float* in_proj_w = (const float*)d_in[2];
    const float* in_proj_b = (const float*)d_in[3];
    const float* out_w     = (const float*)d_in[4];
    const float* out_b     = (const float*)d_in[5];
    const float* ln1_g     = (const float*)d_in[6];
    const float* ln1_b     = (const float*)d_in[7];
    const float* ff1_w     = (const float*)d_in[8];
    const float* ff1_b     = (const float*)d_in[9];
    const float* ff2_w     = (const float*)d_in[10];
    const float* ff2_b     = (const float*)d_in[11];
    const float* ln2_g     = (const float*)d_in[12];
    const float* ln2_b     = (const float*)d_in[13];
    float* x = (float*)d_out;

    __half *wqkv, *wout, *wff1, *wff2, *xh, *attnh;
    cudaGetSymbolAddress((void**)&wqkv, g_wqkv);
    cudaGetSymbolAddress((void**)&wout, g_wout);
    cudaGetSymbolAddress((void**)&wff1, g_wff1);
    cudaGetSymbolAddress((void**)&wff2, g_wff2);
    cudaGetSymbolAddress((void**)&xh,   g_xh);
    cudaGetSymbolAddress((void**)&attnh,g_attnh);

    cudaFuncSetAttribute(gemm_h,     cudaFuncAttributeMaxDynamicSharedMemorySize, SMEM_DYN);
    cudaFuncSetAttribute(attn_fused, cudaFuncAttributeMaxDynamicSharedMemorySize, A_SMEM);
    cudaFuncSetAttribute(ff_fused,   cudaFuncAttributeMaxDynamicSharedMemorySize, F_SMEM);

    cudaMemcpyAsync(x, x_in, sizeof(float) * (size_t)MM * DD,
                    cudaMemcpyDeviceToDevice);
    cvt_all<<<(N_CVT + 255) / 256, 256>>>(x_in, in_proj_w, out_w, ff1_w, ff2_w);

    for (int l = 0; l < NL; l++) {
        // qkv + attention fused -> attnh
        attn_fused<<<BB, 256, A_SMEM>>>(
            xh, wqkv + (size_t)l * 3 * DD * DD, in_proj_b + (size_t)l * 3 * DD,
            mask, attnh);
        // x = LN(x + attnh @ out_w^T + out_b); xh mirror
        gemm_h<<<dim3(1, MM / 128), 256, SMEM_DYN>>>(
            attnh, wout + (size_t)l * DD * DD, out_b + (size_t)l * DD,
            nullptr, x, xh, ln1_g + (size_t)l * DD, ln1_b + (size_t)l * DD, DD, DD, 2);
        // x = LN(x + relu(x@W1^T+b1)@W2^T + b2); xh mirror
        ff_fused<<<MM / 128, 256, F_SMEM>>>(
            xh, wff1 + (size_t)l * FFD * DD, ff1_b + (size_t)l * FFD,
            wff2 + (size_t)l * DD * FFD, ff2_b + (size_t)l * DD,
            x, xh, ln2_g + (size_t)l * DD, ln2_b + (size_t)l * DD);
    }
}